// round 13
// baseline (speedup 1.0000x reference)
#include <cuda_runtime.h>
#include <cuda_bf16.h>

#define N_NODES 50000
#define N_EDGES 800000
#define IN_F 256
#define HFD 128   // HEADS * OUT_FEATS
#define NHEAD 4
#define SCAN_B 196   // ceil(50000/256)
#define GEMM_B 391   // ceil(50000/128)
#define HIST_PER_B 2047  // ceil(800000/391)
#define NBLK 148     // persistent scan+scatter grid (all-resident)
#define LOG2E 1.4426950408889634f

#define SM_STRIDE 36                     // words per row (144B, 16B-aligned)
#define SM_ARR (128 * SM_STRIDE)         // words per operand per stage
#define SMEM_WORDS (4 * SM_ARR)          // A0,B0,A1,B1
#define SMEM_BYTES (SMEM_WORDS * 4)      // 73728 B

// -------- scratch (device globals; no allocation allowed) --------
__device__ float g_feat_hf[N_NODES * HFD];   // projected features [N,128] fp32
__device__ float g_el[N_NODES * NHEAD];      // attn_l dot * log2e  [N,4]
__device__ float g_er[N_NODES * NHEAD];      // attn_r dot * log2e  [N,4]
__device__ int   g_deg[N_NODES];             // per-dst degree (zero-init; re-zeroed each run)
__device__ int   g_rowptr[N_NODES + 1];      // CSR row pointers
__device__ int   g_cursor[N_NODES];          // scatter cursors
__device__ unsigned g_scan_word[SCAN_B];     // decoupled-lookback state (flag<<30 | value)
__device__ int   g_bar;                      // monotonic grid barrier counter
__device__ int2  g_edge[N_EDGES];            // (src, bits(weight)) sorted by dst

__device__ __forceinline__ float ex2(float x) {
    float y;
    asm("ex2.approx.ftz.f32 %0, %1;" : "=f"(y) : "f"(x));
    return y;
}

__device__ __forceinline__ unsigned f2tf32(float f) {
    unsigned u;
    asm("cvt.rna.tf32.f32 %0, %1;" : "=r"(u) : "f"(f));
    return u;
}

// =================================================================
// Kernel 1: tf32 GEMM feat @ W_fc^T + per-block hist slice.
//   double-buffered cp.async; in-place RNA cvt (once per element);
//   el/er computed in the epilogue (pre-scaled by log2e).
//   Hist slice overlaps chunk-0's async-load latency.
// =================================================================
__global__ __launch_bounds__(256) void k_gemm_hist(const float* __restrict__ feat,
                                                   const float* __restrict__ Wfc,
                                                   const float* __restrict__ attn_l,
                                                   const float* __restrict__ attn_r,
                                                   const int* __restrict__ dst) {
    const int tid = threadIdx.x;

    extern __shared__ float smem[];
    float* As0 = smem;
    float* Bs0 = smem + SM_ARR;
    float* As1 = smem + 2 * SM_ARR;
    float* Bs1 = smem + 3 * SM_ARR;

    const int lane = tid & 31;
    const int wid = tid >> 5;
    const int warp_m = wid >> 2;       // 0..1
    const int warp_n = wid & 3;        // 0..3  (== head index h)
    const int row0 = blockIdx.x * 128;

    const int gq = lane >> 2;          // group id 0..7 (row within 8)
    const int tg = lane & 3;           // thread-in-group 0..3

    const int sm_m0 = tid >> 3;        // 0..31 (+32 per i)
    const int sm_seg = tid & 7;        // 16B segment within 128B row-chunk

    // ---- loader: issue one chunk's cp.asyncs into stage st ----
    auto load_chunk = [&](int chunk, int st) {
        const int kglob = chunk * 32;
        float* Adst = st ? As1 : As0;
        float* Bdst = st ? Bs1 : Bs0;
#pragma unroll
        for (int i = 0; i < 4; i++) {
            int m = sm_m0 + i * 32;
            int row = row0 + m;
            if (row >= N_NODES) row = N_NODES - 1;
            const float* srcA = feat + (size_t)row * IN_F + kglob + sm_seg * 4;
            unsigned dA = (unsigned)__cvta_generic_to_shared(&Adst[m * SM_STRIDE + sm_seg * 4]);
            asm volatile("cp.async.ca.shared.global [%0], [%1], 16;" :: "r"(dA), "l"(srcA));
            const float* srcB = Wfc + (size_t)m * IN_F + kglob + sm_seg * 4;
            unsigned dB = (unsigned)__cvta_generic_to_shared(&Bdst[m * SM_STRIDE + sm_seg * 4]);
            asm volatile("cp.async.ca.shared.global [%0], [%1], 16;" :: "r"(dB), "l"(srcB));
        }
        asm volatile("cp.async.commit_group;");
    };

    // ---- in-place cvt: each thread converts exactly what it loaded ----
    auto cvt_stage = [&](int st) {
        float* Adst = st ? As1 : As0;
        float* Bdst = st ? Bs1 : Bs0;
#pragma unroll
        for (int i = 0; i < 4; i++) {
            int m = sm_m0 + i * 32;
            float4* pa = (float4*)&Adst[m * SM_STRIDE + sm_seg * 4];
            float4 va = *pa;
            uint4 ua = make_uint4(f2tf32(va.x), f2tf32(va.y), f2tf32(va.z), f2tf32(va.w));
            *(uint4*)pa = ua;
            float4* pb = (float4*)&Bdst[m * SM_STRIDE + sm_seg * 4];
            float4 vb = *pb;
            uint4 ub = make_uint4(f2tf32(vb.x), f2tf32(vb.y), f2tf32(vb.z), f2tf32(vb.w));
            *(uint4*)pb = ub;
        }
    };

    load_chunk(0, 0);

    // ---- histogram slice (overlaps chunk-0 load latency) ----
    {
        int e0 = blockIdx.x * HIST_PER_B;
        int e1 = e0 + HIST_PER_B;
        if (e1 > N_EDGES) e1 = N_EDGES;
        for (int e = e0 + tid; e < e1; e += 256)
            atomicAdd(&g_deg[__ldg(&dst[e])], 1);
    }

    float acc[4][4][4];                // [mtile][ntile][frag]
#pragma unroll
    for (int i = 0; i < 4; i++)
#pragma unroll
        for (int j = 0; j < 4; j++)
#pragma unroll
            for (int q = 0; q < 4; q++) acc[i][j][q] = 0.f;

    for (int c = 0; c < 8; c++) {
        if (c < 7) {
            load_chunk(c + 1, (c + 1) & 1);
            asm volatile("cp.async.wait_group 1;");
        } else {
            asm volatile("cp.async.wait_group 0;");
        }
        __syncthreads();
        cvt_stage(c & 1);
        __syncthreads();

        const unsigned* Acur = (const unsigned*)((c & 1) ? As1 : As0);
        const unsigned* Bcur = (const unsigned*)((c & 1) ? Bs1 : Bs0);

#pragma unroll
        for (int kk = 0; kk < 4; kk++) {
            const int kb = kk * 8;
            unsigned a[4][4], b[4][2];
#pragma unroll
            for (int mt = 0; mt < 4; mt++) {
                int rs = warp_m * 64 + mt * 16;
                a[mt][0] = Acur[(rs + gq) * SM_STRIDE + kb + tg];
                a[mt][1] = Acur[(rs + gq + 8) * SM_STRIDE + kb + tg];
                a[mt][2] = Acur[(rs + gq) * SM_STRIDE + kb + tg + 4];
                a[mt][3] = Acur[(rs + gq + 8) * SM_STRIDE + kb + tg + 4];
            }
#pragma unroll
            for (int nt = 0; nt < 4; nt++) {
                int ns = warp_n * 32 + nt * 8;
                b[nt][0] = Bcur[(ns + gq) * SM_STRIDE + kb + tg];
                b[nt][1] = Bcur[(ns + gq) * SM_STRIDE + kb + tg + 4];
            }
#pragma unroll
            for (int mt = 0; mt < 4; mt++)
#pragma unroll
                for (int nt = 0; nt < 4; nt++) {
                    asm volatile(
                        "mma.sync.aligned.m16n8k8.row.col.f32.tf32.tf32.f32 "
                        "{%0,%1,%2,%3}, {%4,%5,%6,%7}, {%8,%9}, {%0,%1,%2,%3};"
                        : "+f"(acc[mt][nt][0]), "+f"(acc[mt][nt][1]),
                          "+f"(acc[mt][nt][2]), "+f"(acc[mt][nt][3])
                        : "r"(a[mt][0]), "r"(a[mt][1]), "r"(a[mt][2]), "r"(a[mt][3]),
                          "r"(b[nt][0]), "r"(b[nt][1]));
                }
        }
        __syncthreads();
    }

    // attn vectors for this warp's 8 columns (head = warp_n)
    float al_v[8], ar_v[8];
#pragma unroll
    for (int nt = 0; nt < 4; nt++) {
        int col = warp_n * 32 + nt * 8 + tg * 2;
        al_v[nt * 2 + 0] = __ldg(&attn_l[col]);
        al_v[nt * 2 + 1] = __ldg(&attn_l[col + 1]);
        ar_v[nt * 2 + 0] = __ldg(&attn_r[col]);
        ar_v[nt * 2 + 1] = __ldg(&attn_r[col + 1]);
    }

    // epilogue: store feat_hf + compute el/er (scaled by log2e)
#pragma unroll
    for (int mt = 0; mt < 4; mt++) {
        float pl0 = 0.f, pl1 = 0.f, pr0 = 0.f, pr1 = 0.f;
#pragma unroll
        for (int nt = 0; nt < 4; nt++) {
            int col = warp_n * 32 + nt * 8 + tg * 2;
            int r0 = row0 + warp_m * 64 + mt * 16 + gq;
            if (r0 < N_NODES) {
                float2 v = make_float2(acc[mt][nt][0], acc[mt][nt][1]);
                *(float2*)&g_feat_hf[(size_t)r0 * HFD + col] = v;
            }
            int r1 = r0 + 8;
            if (r1 < N_NODES) {
                float2 v = make_float2(acc[mt][nt][2], acc[mt][nt][3]);
                *(float2*)&g_feat_hf[(size_t)r1 * HFD + col] = v;
            }
            pl0 += acc[mt][nt][0] * al_v[nt * 2] + acc[mt][nt][1] * al_v[nt * 2 + 1];
            pl1 += acc[mt][nt][2] * al_v[nt * 2] + acc[mt][nt][3] * al_v[nt * 2 + 1];
            pr0 += acc[mt][nt][0] * ar_v[nt * 2] + acc[mt][nt][1] * ar_v[nt * 2 + 1];
            pr1 += acc[mt][nt][2] * ar_v[nt * 2] + acc[mt][nt][3] * ar_v[nt * 2 + 1];
        }
#pragma unroll
        for (int o = 1; o < 4; o <<= 1) {
            pl0 += __shfl_xor_sync(0xffffffffu, pl0, o);
            pl1 += __shfl_xor_sync(0xffffffffu, pl1, o);
            pr0 += __shfl_xor_sync(0xffffffffu, pr0, o);
            pr1 += __shfl_xor_sync(0xffffffffu, pr1, o);
        }
        if (tg == 0) {
            int r0 = row0 + warp_m * 64 + mt * 16 + gq;
            if (r0 < N_NODES) {
                g_el[r0 * NHEAD + warp_n] = pl0 * LOG2E;
                g_er[r0 * NHEAD + warp_n] = pr0 * LOG2E;
            }
            int r1 = r0 + 8;
            if (r1 < N_NODES) {
                g_el[r1 * NHEAD + warp_n] = pl1 * LOG2E;
                g_er[r1 * NHEAD + warp_n] = pr1 * LOG2E;
            }
        }
    }
}

// ---------- block-wide exclusive scan helper (256 threads) ----------
__device__ __forceinline__ int block_excl_scan_256(int v) {
    int lane = threadIdx.x & 31, wid = threadIdx.x >> 5;
    int incl = v;
#pragma unroll
    for (int o = 1; o < 32; o <<= 1) {
        int n = __shfl_up_sync(0xffffffffu, incl, o);
        if (lane >= o) incl += n;
    }
    __shared__ int wsum[8];
    if (lane == 31) wsum[wid] = incl;
    __syncthreads();
    int woff = 0;
    if (wid == 0 && lane < 8) {
        int wv = wsum[lane];
        int acc = wv;
#pragma unroll
        for (int o = 1; o < 8; o <<= 1) {
            int n = __shfl_up_sync(0xffu, acc, o);
            if (lane >= o) acc += n;
        }
        wsum[lane] = acc - wv;   // exclusive warp offsets
    }
    __syncthreads();
    woff = wsum[wid];
    return incl - v + woff;
}

// =================================================================
// Kernel 2: persistent scan (decoupled lookback) + grid barrier +
// scatter, in one launch. 148 blocks — all resident, barrier safe.
// =================================================================
__global__ __launch_bounds__(256) void k_scan_scatter(const int* __restrict__ src,
                                                      const int* __restrict__ dst,
                                                      const float* __restrict__ ew) {
    __shared__ int s_agg, s_off;

    // ---- phase 1: scan tiles, grid-stride ----
    for (int tile = blockIdx.x; tile < SCAN_B; tile += NBLK) {
        int idx = tile * 256 + threadIdx.x;
        int v = (idx < N_NODES) ? g_deg[idx] : 0;
        int excl = block_excl_scan_256(v);

        if (threadIdx.x == 255) s_agg = excl + v;
        __syncthreads();

        if (threadIdx.x == 0) {
            unsigned agg = (unsigned)s_agg;
            if (tile == 0) {
                atomicExch(&g_scan_word[0], (2u << 30) | agg);
                s_off = 0;
            } else {
                atomicExch(&g_scan_word[tile], (1u << 30) | agg);
                unsigned sum = 0;
                int i = tile - 1;
                while (i >= 0) {
                    unsigned w = atomicAdd(&g_scan_word[i], 0u);
                    unsigned f = w >> 30;
                    if (f == 0u) continue;
                    sum += w & 0x3FFFFFFFu;
                    if (f == 2u) break;
                    i--;
                }
                atomicExch(&g_scan_word[tile], (2u << 30) | (sum + agg));
                s_off = (int)sum;
            }
        }
        __syncthreads();

        int pos = excl + s_off;
        if (idx < N_NODES) {
            g_rowptr[idx] = pos;
            g_cursor[idx] = pos;
            g_deg[idx] = 0;                       // self-clean for next replay
            if (idx == N_NODES - 1) g_rowptr[N_NODES] = pos + v;
        }
        __syncthreads();    // protect s_agg/s_off reuse next iteration
    }

    // ---- grid barrier (monotonic counter; all 148 blocks resident) ----
    __threadfence();
    __syncthreads();
    if (threadIdx.x == 0) {
        int arrive = atomicAdd(&g_bar, 1) + 1;
        int target = ((arrive - 1) / NBLK + 1) * NBLK;
        while (atomicAdd(&g_bar, 0) < target) {}
    }
    __syncthreads();
    __threadfence();

    // ---- phase 2: scatter edges into CSR order, grid-stride ----
    int t0 = blockIdx.x * 256 + threadIdx.x;
    if (t0 < SCAN_B) g_scan_word[t0] = 0u;        // reset for next replay
    for (int e = t0; e < N_EDGES; e += NBLK * 256) {
        int d = dst[e];
        int pos = atomicAdd(&g_cursor[d], 1);
        g_edge[pos] = make_int2(src[e], __float_as_int(ew[e]));
    }
}

// ---------- per-edge body for k_agg (log2 domain) ----------
__device__ __forceinline__ void agg_edge(const float4& ft, float c2, float w,
                                         const float4& We2,
                                         float4& num, float4& den) {
    float t0 = c2 + w * We2.x;  t0 = fmaxf(t0, 0.2f * t0);
    float t1 = c2 + w * We2.y;  t1 = fmaxf(t1, 0.2f * t1);
    float t2 = c2 + w * We2.z;  t2 = fmaxf(t2, 0.2f * t2);
    float t3 = c2 + w * We2.w;  t3 = fmaxf(t3, 0.2f * t3);
    float e0 = ex2(t0), e1 = ex2(t1), e2 = ex2(t2), e3 = ex2(t3);
    den.x += e0; den.y += e1; den.z += e2; den.w += e3;
    num.x = fmaf(e0, ft.x, num.x);
    num.y = fmaf(e1, ft.y, num.y);
    num.z = fmaf(e2, ft.z, num.z);
    num.w = fmaf(e3, ft.w, num.w);
}

// =================================================================
// Kernel 3: aggregation. One warp per dst node; uniform edge LDGs.
// =================================================================
__global__ __launch_bounds__(256, 6) void k_agg(float* __restrict__ out,
                                                const float* __restrict__ Wedge,
                                                const float* __restrict__ bias) {
    int d = (blockIdx.x * blockDim.x + threadIdx.x) >> 5;
    if (d >= N_NODES) return;
    int lane = threadIdx.x & 31;
    int h = lane >> 3;

    float4 We2 = *(const float4*)&Wedge[lane * 4];
    We2.x *= LOG2E; We2.y *= LOG2E; We2.z *= LOG2E; We2.w *= LOG2E;
    float4 b4 = *(const float4*)&bias[lane * 4];

    int beg = g_rowptr[d];
    int end = g_rowptr[d + 1];
    float er2_h = g_er[d * NHEAD + h];

    float4 num = make_float4(0.f, 0.f, 0.f, 0.f);
    float4 den = make_float4(0.f, 0.f, 0.f, 0.f);

    int j = beg;
    for (; j + 2 <= end; j += 2) {
        int2 e0 = __ldg(&g_edge[j]);
        int2 e1 = __ldg(&g_edge[j + 1]);
        float4 ft0 = *(const float4*)&g_feat_hf[(size_t)e0.x * HFD + lane * 4];
        float4 ft1 = *(const float4*)&g_feat_hf[(size_t)e1.x * HFD + lane * 4];
        float el0 = __ldg(&g_el[e0.x * NHEAD + h]);
        float el1 = __ldg(&g_el[e1.x * NHEAD + h]);

        agg_edge(ft0, el0 + er2_h, __int_as_float(e0.y), We2, num, den);
        agg_edge(ft1, el1 + er2_h, __int_as_float(e1.y), We2, num, den);
    }
    if (j < end) {
        int2 e = __ldg(&g_edge[j]);
        float4 ft = *(const float4*)&g_feat_hf[(size_t)e.x * HFD + lane * 4];
        float el = __ldg(&g_el[e.x * NHEAD + h]);
        agg_edge(ft, el + er2_h, __int_as_float(e.y), We2, num, den);
    }

    float4 o;
    if (end > beg) {
        o.x = num.x / den.x + b4.x;
        o.y = num.y / den.y + b4.y;
        o.z = num.z / den.z + b4.z;
        o.w = num.w / den.w + b4.w;
    } else {
        o = b4;   // isolated node: just bias
    }
    *(float4*)&out[(size_t)d * HFD + lane * 4] = o;
}

// =================================================================
extern "C" void kernel_launch(void* const* d_in, const int* in_sizes, int n_in,
                              void* d_out, int out_size) {
    const float* feat   = (const float*)d_in[0];
    const float* ew     = (const float*)d_in[1];
    const int*   src    = (const int*)d_in[2];
    const int*   dst    = (const int*)d_in[3];
    const float* Wfc    = (const float*)d_in[4];
    const float* Wedge  = (const float*)d_in[5];
    const float* attn_l = (const float*)d_in[6];
    const float* attn_r = (const float*)d_in[7];
    const float* bias   = (const float*)d_in[8];
    float* out = (float*)d_out;

    (void)in_sizes; (void)n_in; (void)out_size;

    static bool attr_set = false;
    if (!attr_set) {
        cudaFuncSetAttribute(k_gemm_hist,
                             cudaFuncAttributeMaxDynamicSharedMemorySize, SMEM_BYTES);
        attr_set = true;
    }

    k_gemm_hist<<<GEMM_B, 256, SMEM_BYTES>>>(feat, Wfc, attn_l, attn_r, dst);
    k_scan_scatter<<<NBLK, 256>>>(src, dst, ew);
    k_agg<<<(N_NODES * 32 + 255) / 256, 256>>>(out, Wedge, bias);
}

// round 14
// speedup vs baseline: 1.1632x; 1.1632x over previous
#include <cuda_runtime.h>
#include <cuda_bf16.h>

#define N_NODES 50000
#define N_EDGES 800000
#define IN_F 256
#define HFD 128   // HEADS * OUT_FEATS
#define NHEAD 4
#define SCAN_B 196   // ceil(50000/256)
#define GEMM_B 391   // ceil(50000/128)
#define EDGE_B 148   // persistent edge-pipeline blocks (wave-1 resident)
#define FUSED_B (EDGE_B + GEMM_B)
#define LOG2E 1.4426950408889634f

#define SM_STRIDE 36                     // words per row (144B, 16B-aligned)
#define SM_ARR (128 * SM_STRIDE)         // words per operand per stage
#define SMEM_WORDS (4 * SM_ARR)          // A0,B0,A1,B1
#define SMEM_BYTES (SMEM_WORDS * 4)      // 73728 B

// -------- scratch (device globals; no allocation allowed) --------
__device__ float g_feat_hf[N_NODES * HFD];   // projected features [N,128] fp32
__device__ float g_el[N_NODES * NHEAD];      // attn_l dot * log2e  [N,4]
__device__ float g_er[N_NODES * NHEAD];      // attn_r dot * log2e  [N,4]
__device__ int   g_deg[N_NODES];             // per-dst degree (zero-init; re-zeroed by scan)
__device__ int   g_rowptr[N_NODES + 1];      // CSR row pointers
__device__ int   g_cursor[N_NODES];          // scatter cursors
__device__ unsigned g_scan_word[SCAN_B];     // decoupled-lookback state (flag<<30 | value)
__device__ int   g_bar;                      // monotonic grid-barrier counter
__device__ int2  g_edge[N_EDGES];            // (src, bits(weight)) sorted by dst

__device__ __forceinline__ float ex2(float x) {
    float y;
    asm("ex2.approx.ftz.f32 %0, %1;" : "=f"(y) : "f"(x));
    return y;
}

__device__ __forceinline__ unsigned f2tf32(float f) {
    unsigned u;
    asm("cvt.rna.tf32.f32 %0, %1;" : "=r"(u) : "f"(f));
    return u;
}

// ---------- block-wide exclusive scan helper (256 threads) ----------
__device__ __forceinline__ int block_excl_scan_256(int v) {
    int lane = threadIdx.x & 31, wid = threadIdx.x >> 5;
    int incl = v;
#pragma unroll
    for (int o = 1; o < 32; o <<= 1) {
        int n = __shfl_up_sync(0xffffffffu, incl, o);
        if (lane >= o) incl += n;
    }
    __shared__ int wsum[8];
    if (lane == 31) wsum[wid] = incl;
    __syncthreads();
    int woff = 0;
    if (wid == 0 && lane < 8) {
        int wv = wsum[lane];
        int acc = wv;
#pragma unroll
        for (int o = 1; o < 8; o <<= 1) {
            int n = __shfl_up_sync(0xffu, acc, o);
            if (lane >= o) acc += n;
        }
        wsum[lane] = acc - wv;   // exclusive warp offsets
    }
    __syncthreads();
    woff = wsum[wid];
    return incl - v + woff;
}

// ---------- monotonic grid barrier among the EDGE_B edge blocks ----------
__device__ __forceinline__ void edge_grid_barrier() {
    __syncthreads();
    __threadfence();
    if (threadIdx.x == 0) {
        int arrive = atomicAdd(&g_bar, 1) + 1;
        int target = ((arrive - 1) / EDGE_B + 1) * EDGE_B;
        while (atomicAdd(&g_bar, 0) < target) {}
    }
    __syncthreads();
    __threadfence();
}

// =================================================================
// Kernel 1 (fused):
//  blocks [0, EDGE_B): persistent edge pipeline
//      hist -> barrier -> lookback scan -> barrier -> scatter
//      (independent of the GEMM; hidden in its shadow)
//  blocks [EDGE_B, FUSED_B): tf32 GEMM feat @ W_fc^T
//      double-buffered cp.async; RNA cvt at fragment load;
//      el/er epilogue (pre-scaled by log2e).
// =================================================================
__global__ __launch_bounds__(256) void k_fused(const float* __restrict__ feat,
                                               const float* __restrict__ Wfc,
                                               const float* __restrict__ attn_l,
                                               const float* __restrict__ attn_r,
                                               const int* __restrict__ src,
                                               const int* __restrict__ dst,
                                               const float* __restrict__ ew) {
    const int tid = threadIdx.x;

    if (blockIdx.x < EDGE_B) {
        // ================= edge pipeline =================
        const int bid = blockIdx.x;
        __shared__ int s_agg, s_off;

        // ---- phase 0: histogram (grid-stride over edges) ----
        for (int e = bid * 256 + tid; e < N_EDGES; e += EDGE_B * 256)
            atomicAdd(&g_deg[__ldg(&dst[e])], 1);

        edge_grid_barrier();

        // ---- phase 1: decoupled-lookback scan ----
        for (int tile = bid; tile < SCAN_B; tile += EDGE_B) {
            int idx = tile * 256 + tid;
            int v = (idx < N_NODES) ? g_deg[idx] : 0;
            int excl = block_excl_scan_256(v);

            if (tid == 255) s_agg = excl + v;
            __syncthreads();

            if (tid == 0) {
                unsigned agg = (unsigned)s_agg;
                if (tile == 0) {
                    atomicExch(&g_scan_word[0], (2u << 30) | agg);
                    s_off = 0;
                } else {
                    atomicExch(&g_scan_word[tile], (1u << 30) | agg);
                    unsigned sum = 0;
                    int i = tile - 1;
                    while (i >= 0) {
                        unsigned w = atomicAdd(&g_scan_word[i], 0u);
                        unsigned f = w >> 30;
                        if (f == 0u) continue;
                        sum += w & 0x3FFFFFFFu;
                        if (f == 2u) break;
                        i--;
                    }
                    atomicExch(&g_scan_word[tile], (2u << 30) | (sum + agg));
                    s_off = (int)sum;
                }
            }
            __syncthreads();

            int pos = excl + s_off;
            if (idx < N_NODES) {
                g_rowptr[idx] = pos;
                g_cursor[idx] = pos;
                g_deg[idx] = 0;                   // self-clean for next replay
                if (idx == N_NODES - 1) g_rowptr[N_NODES] = pos + v;
            }
            __syncthreads();    // protect s_agg/s_off reuse
        }

        edge_grid_barrier();

        // ---- phase 2: scatter into CSR order ----
        int t0 = bid * 256 + tid;
        if (t0 < SCAN_B) g_scan_word[t0] = 0u;    // reset for next replay
        for (int e = t0; e < N_EDGES; e += EDGE_B * 256) {
            int d = dst[e];
            int pos = atomicAdd(&g_cursor[d], 1);
            g_edge[pos] = make_int2(src[e], __float_as_int(ew[e]));
        }
        return;
    }

    // ================= GEMM part (R12 configuration) =================
    extern __shared__ float smem[];
    float* As0 = smem;
    float* Bs0 = smem + SM_ARR;
    float* As1 = smem + 2 * SM_ARR;
    float* Bs1 = smem + 3 * SM_ARR;

    const int lane = tid & 31;
    const int wid = tid >> 5;
    const int warp_m = wid >> 2;       // 0..1
    const int warp_n = wid & 3;        // 0..3  (== head index h)
    const int row0 = (blockIdx.x - EDGE_B) * 128;

    float acc[4][4][4];                // [mtile][ntile][frag]
#pragma unroll
    for (int i = 0; i < 4; i++)
#pragma unroll
        for (int j = 0; j < 4; j++)
#pragma unroll
            for (int q = 0; q < 4; q++) acc[i][j][q] = 0.f;

    const int gq = lane >> 2;          // group id 0..7 (row within 8)
    const int tg = lane & 3;           // thread-in-group 0..3

    const int sm_m0 = tid >> 3;        // 0..31 (+32 per i)
    const int sm_seg = tid & 7;        // 16B segment within 128B row-chunk

    auto load_chunk = [&](int chunk, int st) {
        const int kglob = chunk * 32;
        float* Adst = st ? As1 : As0;
        float* Bdst = st ? Bs1 : Bs0;
#pragma unroll
        for (int i = 0; i < 4; i++) {
            int m = sm_m0 + i * 32;
            int row = row0 + m;
            if (row >= N_NODES) row = N_NODES - 1;
            const float* srcA = feat + (size_t)row * IN_F + kglob + sm_seg * 4;
            unsigned dA = (unsigned)__cvta_generic_to_shared(&Adst[m * SM_STRIDE + sm_seg * 4]);
            asm volatile("cp.async.ca.shared.global [%0], [%1], 16;" :: "r"(dA), "l"(srcA));
            const float* srcB = Wfc + (size_t)m * IN_F + kglob + sm_seg * 4;
            unsigned dB = (unsigned)__cvta_generic_to_shared(&Bdst[m * SM_STRIDE + sm_seg * 4]);
            asm volatile("cp.async.ca.shared.global [%0], [%1], 16;" :: "r"(dB), "l"(srcB));
        }
        asm volatile("cp.async.commit_group;");
    };

    load_chunk(0, 0);

    for (int c = 0; c < 8; c++) {
        if (c < 7) {
            load_chunk(c + 1, (c + 1) & 1);
            asm volatile("cp.async.wait_group 1;");
        } else {
            asm volatile("cp.async.wait_group 0;");
        }
        __syncthreads();

        const float* Acur = (c & 1) ? As1 : As0;
        const float* Bcur = (c & 1) ? Bs1 : Bs0;

#pragma unroll
        for (int kk = 0; kk < 4; kk++) {
            const int kb = kk * 8;
            unsigned a[4][4], b[4][2];
#pragma unroll
            for (int mt = 0; mt < 4; mt++) {
                int rs = warp_m * 64 + mt * 16;
                a[mt][0] = f2tf32(Acur[(rs + gq) * SM_STRIDE + kb + tg]);
                a[mt][1] = f2tf32(Acur[(rs + gq + 8) * SM_STRIDE + kb + tg]);
                a[mt][2] = f2tf32(Acur[(rs + gq) * SM_STRIDE + kb + tg + 4]);
                a[mt][3] = f2tf32(Acur[(rs + gq + 8) * SM_STRIDE + kb + tg + 4]);
            }
#pragma unroll
            for (int nt = 0; nt < 4; nt++) {
                int ns = warp_n * 32 + nt * 8;
                b[nt][0] = f2tf32(Bcur[(ns + gq) * SM_STRIDE + kb + tg]);
                b[nt][1] = f2tf32(Bcur[(ns + gq) * SM_STRIDE + kb + tg + 4]);
            }
#pragma unroll
            for (int mt = 0; mt < 4; mt++)
#pragma unroll
                for (int nt = 0; nt < 4; nt++) {
                    asm volatile(
                        "mma.sync.aligned.m16n8k8.row.col.f32.tf32.tf32.f32 "
                        "{%0,%1,%2,%3}, {%4,%5,%6,%7}, {%8,%9}, {%0,%1,%2,%3};"
                        : "+f"(acc[mt][nt][0]), "+f"(acc[mt][nt][1]),
                          "+f"(acc[mt][nt][2]), "+f"(acc[mt][nt][3])
                        : "r"(a[mt][0]), "r"(a[mt][1]), "r"(a[mt][2]), "r"(a[mt][3]),
                          "r"(b[nt][0]), "r"(b[nt][1]));
                }
        }
        __syncthreads();
    }

    // attn vectors for this warp's 8 columns (head = warp_n)
    float al_v[8], ar_v[8];
#pragma unroll
    for (int nt = 0; nt < 4; nt++) {
        int col = warp_n * 32 + nt * 8 + tg * 2;
        al_v[nt * 2 + 0] = __ldg(&attn_l[col]);
        al_v[nt * 2 + 1] = __ldg(&attn_l[col + 1]);
        ar_v[nt * 2 + 0] = __ldg(&attn_r[col]);
        ar_v[nt * 2 + 1] = __ldg(&attn_r[col + 1]);
    }

    // epilogue: store feat_hf + compute el/er (scaled by log2e)
#pragma unroll
    for (int mt = 0; mt < 4; mt++) {
        float pl0 = 0.f, pl1 = 0.f, pr0 = 0.f, pr1 = 0.f;
#pragma unroll
        for (int nt = 0; nt < 4; nt++) {
            int col = warp_n * 32 + nt * 8 + tg * 2;
            int r0 = row0 + warp_m * 64 + mt * 16 + gq;
            if (r0 < N_NODES) {
                float2 v = make_float2(acc[mt][nt][0], acc[mt][nt][1]);
                *(float2*)&g_feat_hf[(size_t)r0 * HFD + col] = v;
            }
            int r1 = r0 + 8;
            if (r1 < N_NODES) {
                float2 v = make_float2(acc[mt][nt][2], acc[mt][nt][3]);
                *(float2*)&g_feat_hf[(size_t)r1 * HFD + col] = v;
            }
            pl0 += acc[mt][nt][0] * al_v[nt * 2] + acc[mt][nt][1] * al_v[nt * 2 + 1];
            pl1 += acc[mt][nt][2] * al_v[nt * 2] + acc[mt][nt][3] * al_v[nt * 2 + 1];
            pr0 += acc[mt][nt][0] * ar_v[nt * 2] + acc[mt][nt][1] * ar_v[nt * 2 + 1];
            pr1 += acc[mt][nt][2] * ar_v[nt * 2] + acc[mt][nt][3] * ar_v[nt * 2 + 1];
        }
#pragma unroll
        for (int o = 1; o < 4; o <<= 1) {
            pl0 += __shfl_xor_sync(0xffffffffu, pl0, o);
            pl1 += __shfl_xor_sync(0xffffffffu, pl1, o);
            pr0 += __shfl_xor_sync(0xffffffffu, pr0, o);
            pr1 += __shfl_xor_sync(0xffffffffu, pr1, o);
        }
        if (tg == 0) {
            int r0 = row0 + warp_m * 64 + mt * 16 + gq;
            if (r0 < N_NODES) {
                g_el[r0 * NHEAD + warp_n] = pl0 * LOG2E;
                g_er[r0 * NHEAD + warp_n] = pr0 * LOG2E;
            }
            int r1 = r0 + 8;
            if (r1 < N_NODES) {
                g_el[r1 * NHEAD + warp_n] = pl1 * LOG2E;
                g_er[r1 * NHEAD + warp_n] = pr1 * LOG2E;
            }
        }
    }
}

// ---------- per-edge body for k_agg (log2 domain) ----------
__device__ __forceinline__ void agg_edge(const float4& ft, float c2, float w,
                                         const float4& We2,
                                         float4& num, float4& den) {
    float t0 = c2 + w * We2.x;  t0 = fmaxf(t0, 0.2f * t0);
    float t1 = c2 + w * We2.y;  t1 = fmaxf(t1, 0.2f * t1);
    float t2 = c2 + w * We2.z;  t2 = fmaxf(t2, 0.2f * t2);
    float t3 = c2 + w * We2.w;  t3 = fmaxf(t3, 0.2f * t3);
    float e0 = ex2(t0), e1 = ex2(t1), e2 = ex2(t2), e3 = ex2(t3);
    den.x += e0; den.y += e1; den.z += e2; den.w += e3;
    num.x = fmaf(e0, ft.x, num.x);
    num.y = fmaf(e1, ft.y, num.y);
    num.z = fmaf(e2, ft.z, num.z);
    num.w = fmaf(e3, ft.w, num.w);
}

// =================================================================
// Kernel 2: aggregation. One warp per dst node; uniform edge LDGs.
// =================================================================
__global__ __launch_bounds__(256, 6) void k_agg(float* __restrict__ out,
                                                const float* __restrict__ Wedge,
                                                const float* __restrict__ bias) {
    int d = (blockIdx.x * blockDim.x + threadIdx.x) >> 5;
    if (d >= N_NODES) return;
    int lane = threadIdx.x & 31;
    int h = lane >> 3;

    float4 We2 = *(const float4*)&Wedge[lane * 4];
    We2.x *= LOG2E; We2.y *= LOG2E; We2.z *= LOG2E; We2.w *= LOG2E;
    float4 b4 = *(const float4*)&bias[lane * 4];

    int beg = g_rowptr[d];
    int end = g_rowptr[d + 1];
    float er2_h = g_er[d * NHEAD + h];

    float4 num = make_float4(0.f, 0.f, 0.f, 0.f);
    float4 den = make_float4(0.f, 0.f, 0.f, 0.f);

    int j = beg;
    for (; j + 2 <= end; j += 2) {
        int2 e0 = __ldg(&g_edge[j]);
        int2 e1 = __ldg(&g_edge[j + 1]);
        float4 ft0 = *(const float4*)&g_feat_hf[(size_t)e0.x * HFD + lane * 4];
        float4 ft1 = *(const float4*)&g_feat_hf[(size_t)e1.x * HFD + lane * 4];
        float el0 = __ldg(&g_el[e0.x * NHEAD + h]);
        float el1 = __ldg(&g_el[e1.x * NHEAD + h]);

        agg_edge(ft0, el0 + er2_h, __int_as_float(e0.y), We2, num, den);
        agg_edge(ft1, el1 + er2_h, __int_as_float(e1.y), We2, num, den);
    }
    if (j < end) {
        int2 e = __ldg(&g_edge[j]);
        float4 ft = *(const float4*)&g_feat_hf[(size_t)e.x * HFD + lane * 4];
        float el = __ldg(&g_el[e.x * NHEAD + h]);
        agg_edge(ft, el + er2_h, __int_as_float(e.y), We2, num, den);
    }

    float4 o;
    if (end > beg) {
        o.x = num.x / den.x + b4.x;
        o.y = num.y / den.y + b4.y;
        o.z = num.z / den.z + b4.z;
        o.w = num.w / den.w + b4.w;
    } else {
        o = b4;   // isolated node: just bias
    }
    *(float4*)&out[(size_t)d * HFD + lane * 4] = o;
}

// =================================================================
extern "C" void kernel_launch(void* const* d_in, const int* in_sizes, int n_in,
                              void* d_out, int out_size) {
    const float* feat   = (const float*)d_in[0];
    const float* ew     = (const float*)d_in[1];
    const int*   src    = (const int*)d_in[2];
    const int*   dst    = (const int*)d_in[3];
    const float* Wfc    = (const float*)d_in[4];
    const float* Wedge  = (const float*)d_in[5];
    const float* attn_l = (const float*)d_in[6];
    const float* attn_r = (const float*)d_in[7];
    const float* bias   = (const float*)d_in[8];
    float* out = (float*)d_out;

    (void)in_sizes; (void)n_in; (void)out_size;

    static bool attr_set = false;
    if (!attr_set) {
        cudaFuncSetAttribute(k_fused,
                             cudaFuncAttributeMaxDynamicSharedMemorySize, SMEM_BYTES);
        attr_set = true;
    }

    k_fused<<<FUSED_B, 256, SMEM_BYTES>>>(feat, Wfc, attn_l, attn_r, src, dst, ew);
    k_agg<<<(N_NODES * 32 + 255) / 256, 256>>>(out, Wedge, bias);
}